// round 2
// baseline (speedup 1.0000x reference)
#include <cuda_runtime.h>
#include <math.h>

// Problem constants
// B=2, S=2048, HID=2048, H=32, KVH=8, D=64, G=4, ROT=32

#define NBATCH 2
#define SEQ    2048
#define HID    2048
#define NHEAD  32
#define NKV    8
#define HDIM   64

// Scratch (allocation-free rule: device globals)
__device__ float g_q[NBATCH*SEQ*NHEAD*HDIM];   // 33.5 MB
__device__ float g_k[NBATCH*SEQ*NKV*HDIM];     //  8.4 MB
__device__ float g_v[NBATCH*SEQ*NKV*HDIM];     //  8.4 MB
__device__ float g_att[NBATCH*SEQ*NHEAD*HDIM]; // 33.5 MB

// ---------------------------------------------------------------------------
// GEMM:  C[M,N] = A[M,K] @ W[N,K]^T   (A, W, C all row-major)
// 128x128 tile, BK=16, 256 threads, 8x8 register blocking.
// Requires M%128==0, N%128==0, K%16==0 (true for all our shapes).
// ---------------------------------------------------------------------------
__global__ __launch_bounds__(256)
void gemm_nt(const float* __restrict__ A, const float* __restrict__ W,
             float* __restrict__ C, int M, int N, int K) {
    __shared__ float As[16][128];
    __shared__ float Bs[16][128];
    const int tid  = threadIdx.x;
    const int bm   = blockIdx.y * 128;
    const int bn   = blockIdx.x * 128;
    const int lr   = tid >> 2;          // 0..63
    const int lc   = (tid & 3) << 2;    // 0,4,8,12
    const int trow = (tid >> 4) << 3;   // 0..120
    const int tcol = (tid & 15) << 3;   // 0..120

    float acc[8][8];
#pragma unroll
    for (int i = 0; i < 8; i++)
#pragma unroll
        for (int j = 0; j < 8; j++) acc[i][j] = 0.f;

    for (int k0 = 0; k0 < K; k0 += 16) {
#pragma unroll
        for (int p = 0; p < 2; p++) {
            int row = lr + p * 64;
            float4 va = *(const float4*)(A + (size_t)(bm + row) * K + k0 + lc);
            As[lc + 0][row] = va.x; As[lc + 1][row] = va.y;
            As[lc + 2][row] = va.z; As[lc + 3][row] = va.w;
            float4 vb = *(const float4*)(W + (size_t)(bn + row) * K + k0 + lc);
            Bs[lc + 0][row] = vb.x; Bs[lc + 1][row] = vb.y;
            Bs[lc + 2][row] = vb.z; Bs[lc + 3][row] = vb.w;
        }
        __syncthreads();
#pragma unroll
        for (int kk = 0; kk < 16; kk++) {
            float af[8], bf[8];
            *(float4*)&af[0] = *(const float4*)&As[kk][trow];
            *(float4*)&af[4] = *(const float4*)&As[kk][trow + 4];
            *(float4*)&bf[0] = *(const float4*)&Bs[kk][tcol];
            *(float4*)&bf[4] = *(const float4*)&Bs[kk][tcol + 4];
#pragma unroll
            for (int i = 0; i < 8; i++)
#pragma unroll
                for (int j = 0; j < 8; j++)
                    acc[i][j] += af[i] * bf[j];
        }
        __syncthreads();
    }

#pragma unroll
    for (int i = 0; i < 8; i++) {
        float* dst = C + (size_t)(bm + trow + i) * N + bn + tcol;
        *(float4*)dst       = make_float4(acc[i][0], acc[i][1], acc[i][2], acc[i][3]);
        *(float4*)(dst + 4) = make_float4(acc[i][4], acc[i][5], acc[i][6], acc[i][7]);
    }
}

// ---------------------------------------------------------------------------
// Partial RoPE (first ROT=32 dims), in place.
// x: [B*S, nheads, 64]. cos/sin: [B*S, 32] with cos[p] == cos[p+16].
// out[p]    = x[p]*cos[p]    - x[p+16]*sin[p]
// out[p+16] = x[p+16]*cos[p] + x[p]   *sin[p]
// ---------------------------------------------------------------------------
__global__ void rope_kernel(float* __restrict__ x, const float* __restrict__ ct,
                            const float* __restrict__ st, int nheads, int total) {
    int idx = blockIdx.x * blockDim.x + threadIdx.x;
    if (idx >= total) return;
    int p  = idx & 15;
    int h  = (idx >> 4) % nheads;
    int bs = idx / (16 * nheads);
    float c = ct[bs * 32 + p];
    float s = st[bs * 32 + p];
    size_t base = ((size_t)bs * nheads + h) * 64;
    float x0 = x[base + p];
    float x1 = x[base + p + 16];
    x[base + p]      = x0 * c - x1 * s;
    x[base + p + 16] = x1 * c + x0 * s;
}

// ---------------------------------------------------------------------------
// Flash attention (fp32, causal, GQA).
// Grid: (S/64, B*H). Block: 256 threads. 64x64 Q tile, 64x64 K tiles.
// Smem layouts (stride 68 keeps float4 alignment, spreads banks):
//   Qst[d][m] (transposed), Kst[d][n] (transposed), Vs[n][d], St[n][m].
// ---------------------------------------------------------------------------
#define SSTR 68
#define NEGBIG (-1e30f)

__global__ __launch_bounds__(256)
void flash_kernel(const float* __restrict__ q, const float* __restrict__ k,
                  const float* __restrict__ v, float* __restrict__ o) {
    extern __shared__ float sm[];
    float* Qst   = sm;                 // [64][SSTR]
    float* Kst   = Qst + 64 * SSTR;    // [64][SSTR]
    float* Vs    = Kst + 64 * SSTR;    // [64][SSTR]
    float* St    = Vs  + 64 * SSTR;    // [64][SSTR]
    float* row_m = St  + 64 * SSTR;    // [64]
    float* row_l = row_m + 64;         // [64]
    float* row_a = row_l + 64;         // [64]

    const int tid = threadIdx.x;
    const int qt  = blockIdx.x;        // query tile 0..31
    const int bh  = blockIdx.y;        // b*32 + h
    const int b   = bh >> 5;
    const int h   = bh & 31;
    const int kvh = h >> 2;            // G = 4
    const int tr  = tid >> 4;          // 0..15
    const int tc  = tid & 15;          // 0..15
    const int lr  = tid >> 2;          // 0..63 (load row)
    const int ld0 = (tid & 3) << 4;    // 0,16,32,48 (load dim base)

    // Load Q tile, pre-scaled by 1/sqrt(64)
    {
        const float* src = q + ((size_t)(b * SEQ + qt * 64 + lr) * (NHEAD * HDIM))
                             + h * HDIM + ld0;
#pragma unroll
        for (int u = 0; u < 4; u++) {
            float4 va = *(const float4*)(src + u * 4);
            int d0 = ld0 + u * 4;
            Qst[(d0 + 0) * SSTR + lr] = va.x * 0.125f;
            Qst[(d0 + 1) * SSTR + lr] = va.y * 0.125f;
            Qst[(d0 + 2) * SSTR + lr] = va.z * 0.125f;
            Qst[(d0 + 3) * SSTR + lr] = va.w * 0.125f;
        }
    }
    if (tid < 64) { row_m[tid] = NEGBIG; row_l[tid] = 0.f; }

    float acc[4][4];
#pragma unroll
    for (int i = 0; i < 4; i++)
#pragma unroll
        for (int j = 0; j < 4; j++) acc[i][j] = 0.f;

    __syncthreads();

    for (int kt = 0; kt <= qt; kt++) {
        // Load K (transposed) and V tiles
        {
            const float* ks = k + ((size_t)(b * SEQ + kt * 64 + lr) * (NKV * HDIM))
                                + kvh * HDIM + ld0;
            const float* vs = v + ((size_t)(b * SEQ + kt * 64 + lr) * (NKV * HDIM))
                                + kvh * HDIM + ld0;
#pragma unroll
            for (int u = 0; u < 4; u++) {
                int d0 = ld0 + u * 4;
                float4 va = *(const float4*)(ks + u * 4);
                Kst[(d0 + 0) * SSTR + lr] = va.x;
                Kst[(d0 + 1) * SSTR + lr] = va.y;
                Kst[(d0 + 2) * SSTR + lr] = va.z;
                Kst[(d0 + 3) * SSTR + lr] = va.w;
                float4 vb = *(const float4*)(vs + u * 4);
                *(float4*)&Vs[lr * SSTR + d0] = vb;
            }
        }
        __syncthreads();

        // S = Q @ K^T  (each thread: 4x4 micro-tile)
        float s[4][4];
#pragma unroll
        for (int i = 0; i < 4; i++)
#pragma unroll
            for (int j = 0; j < 4; j++) s[i][j] = 0.f;
#pragma unroll 8
        for (int d = 0; d < 64; d++) {
            float qa[4], kb[4];
            *(float4*)qa = *(const float4*)&Qst[d * SSTR + tr * 4];
            *(float4*)kb = *(const float4*)&Kst[d * SSTR + tc * 4];
#pragma unroll
            for (int i = 0; i < 4; i++)
#pragma unroll
                for (int j = 0; j < 4; j++)
                    s[i][j] += qa[i] * kb[j];
        }
        const bool diag = (kt == qt);
#pragma unroll
        for (int j = 0; j < 4; j++) {
            int n = tc * 4 + j;
            float4 col;
            float* cp = &col.x;
#pragma unroll
            for (int i = 0; i < 4; i++) {
                int m = tr * 4 + i;
                float sv = s[i][j];
                if (diag && n > m) sv = NEGBIG;
                cp[i] = sv;
            }
            *(float4*)&St[n * SSTR + tr * 4] = col;
        }
        __syncthreads();

        // Online softmax: one thread per row
        if (tid < 64) {
            const int r = tid;
            float mx = row_m[r];
#pragma unroll 8
            for (int n = 0; n < 64; n++) mx = fmaxf(mx, St[n * SSTR + r]);
            float alpha = __expf(row_m[r] - mx);
            float l = row_l[r] * alpha;
            float sum = 0.f;
#pragma unroll 8
            for (int n = 0; n < 64; n++) {
                float p = __expf(St[n * SSTR + r] - mx);
                St[n * SSTR + r] = p;
                sum += p;
            }
            row_l[r] = l + sum;
            row_m[r] = mx;
            row_a[r] = alpha;
        }
        __syncthreads();

        // Rescale acc, accumulate P @ V
        float al[4];
#pragma unroll
        for (int i = 0; i < 4; i++) al[i] = row_a[tr * 4 + i];
#pragma unroll
        for (int i = 0; i < 4; i++)
#pragma unroll
            for (int j = 0; j < 4; j++) acc[i][j] *= al[i];
#pragma unroll 8
        for (int n = 0; n < 64; n++) {
            float p[4], vv[4];
            *(float4*)p  = *(const float4*)&St[n * SSTR + tr * 4];
            *(float4*)vv = *(const float4*)&Vs[n * SSTR + tc * 4];
#pragma unroll
            for (int i = 0; i < 4; i++)
#pragma unroll
                for (int j = 0; j < 4; j++)
                    acc[i][j] += p[i] * vv[j];
        }
        __syncthreads();
    }

    // Normalize and write output: [b, s, h, d]
#pragma unroll
    for (int i = 0; i < 4; i++) {
        int m = tr * 4 + i;
        float inv = 1.f / row_l[m];
        float* dst = o + ((size_t)(b * SEQ + qt * 64 + m) * (NHEAD * HDIM))
                       + h * HDIM + tc * 4;
        *(float4*)dst = make_float4(acc[i][0] * inv, acc[i][1] * inv,
                                    acc[i][2] * inv, acc[i][3] * inv);
    }
}

// ---------------------------------------------------------------------------
// Host launcher
// Inputs: 0 hidden[B,S,HID] 1 cos[B,S,32] 2 sin 3 mask(unused)
//         4 Wq[2048,2048] 5 Wk[512,2048] 6 Wv[512,2048] 7 Wo[2048,2048]
// ---------------------------------------------------------------------------
extern "C" void kernel_launch(void* const* d_in, const int* in_sizes, int n_in,
                              void* d_out, int out_size) {
    const float* hidden = (const float*)d_in[0];
    const float* cosb   = (const float*)d_in[1];
    const float* sinb   = (const float*)d_in[2];
    const float* Wq     = (const float*)d_in[4];
    const float* Wk     = (const float*)d_in[5];
    const float* Wv     = (const float*)d_in[6];
    const float* Wo     = (const float*)d_in[7];
    float* out = (float*)d_out;

    float *qp, *kp, *vp, *ap;
    cudaGetSymbolAddress((void**)&qp, g_q);
    cudaGetSymbolAddress((void**)&kp, g_k);
    cudaGetSymbolAddress((void**)&vp, g_v);
    cudaGetSymbolAddress((void**)&ap, g_att);

    const int M = NBATCH * SEQ;  // 4096
    dim3 blk(256);

    // QKV projections
    gemm_nt<<<dim3(2048 / 128, M / 128), blk>>>(hidden, Wq, qp, M, 2048, 2048);
    gemm_nt<<<dim3(512  / 128, M / 128), blk>>>(hidden, Wk, kp, M, 512, 2048);
    gemm_nt<<<dim3(512  / 128, M / 128), blk>>>(hidden, Wv, vp, M, 512, 2048);

    // Partial RoPE on q and k
    int totq = M * NHEAD * 16;
    rope_kernel<<<(totq + 255) / 256, 256>>>(qp, cosb, sinb, NHEAD, totq);
    int totk = M * NKV * 16;
    rope_kernel<<<(totk + 255) / 256, 256>>>(kp, cosb, sinb, NKV, totk);

    // Flash attention
    size_t smem = (size_t)4 * 64 * SSTR * sizeof(float) + 3 * 64 * sizeof(float);
    cudaFuncSetAttribute(flash_kernel, cudaFuncAttributeMaxDynamicSharedMemorySize,
                         (int)smem);
    flash_kernel<<<dim3(SEQ / 64, NBATCH * NHEAD), blk, smem>>>(qp, kp, vp, ap);

    // Output projection -> d_out
    gemm_nt<<<dim3(2048 / 128, M / 128), blk>>>(ap, Wo, out, M, 2048, 2048);
}

// round 4
// speedup vs baseline: 1.7076x; 1.7076x over previous
#include <cuda_runtime.h>
#include <cuda_bf16.h>
#include <cstdint>
#include <math.h>

// Problem: B=2, S=2048, HID=2048, H=32, KVH=8, D=64, G=4, ROT=32
#define NBATCH 2
#define SEQ    2048
#define HID    2048
#define NHEAD  32
#define NKV    8
#define HDIM   64

// ---------------------------------------------------------------------------
// Scratch (device globals; no allocations allowed)
// ---------------------------------------------------------------------------
__device__ float g_q[NBATCH*SEQ*NHEAD*HDIM];
__device__ float g_k[NBATCH*SEQ*NKV*HDIM];
__device__ float g_v[NBATCH*SEQ*NKV*HDIM];
__device__ float g_att[NBATCH*SEQ*NHEAD*HDIM];

// bf16 split buffers (hi/lo)
__device__ __nv_bfloat16 g_ah[4096*2048], g_al[4096*2048];     // hidden
__device__ __nv_bfloat16 g_oh[4096*2048], g_ol[4096*2048];     // attn out
__device__ __nv_bfloat16 g_wqh[2048*2048], g_wql[2048*2048];
__device__ __nv_bfloat16 g_wkh[512*2048],  g_wkl[512*2048];
__device__ __nv_bfloat16 g_wvh[512*2048],  g_wvl[512*2048];
__device__ __nv_bfloat16 g_woh[2048*2048], g_wol[2048*2048];

// ---------------------------------------------------------------------------
// fp32 -> (bf16 hi, bf16 lo) split, vectorized x4
// ---------------------------------------------------------------------------
__global__ void split_kernel(const float* __restrict__ x,
                             __nv_bfloat16* __restrict__ hi,
                             __nv_bfloat16* __restrict__ lo, int n4) {
    int i = blockIdx.x * blockDim.x + threadIdx.x;
    if (i >= n4) return;
    float4 v = ((const float4*)x)[i];
    __nv_bfloat16 h0 = __float2bfloat16(v.x);
    __nv_bfloat16 h1 = __float2bfloat16(v.y);
    __nv_bfloat16 h2 = __float2bfloat16(v.z);
    __nv_bfloat16 h3 = __float2bfloat16(v.w);
    __nv_bfloat16 l0 = __float2bfloat16(v.x - __bfloat162float(h0));
    __nv_bfloat16 l1 = __float2bfloat16(v.y - __bfloat162float(h1));
    __nv_bfloat16 l2 = __float2bfloat16(v.z - __bfloat162float(h2));
    __nv_bfloat16 l3 = __float2bfloat16(v.w - __bfloat162float(h3));
    __nv_bfloat162* hp = (__nv_bfloat162*)(hi + (size_t)i * 4);
    __nv_bfloat162* lp = (__nv_bfloat162*)(lo + (size_t)i * 4);
    hp[0] = __nv_bfloat162(h0, h1); hp[1] = __nv_bfloat162(h2, h3);
    lp[0] = __nv_bfloat162(l0, l1); lp[1] = __nv_bfloat162(l2, l3);
}

// ---------------------------------------------------------------------------
// mma.sync helpers
// ---------------------------------------------------------------------------
__device__ __forceinline__ void mma_bf16(float* c, const uint32_t* a, const uint32_t* b) {
    asm volatile(
        "mma.sync.aligned.m16n8k16.row.col.f32.bf16.bf16.f32 "
        "{%0,%1,%2,%3}, {%4,%5,%6,%7}, {%8,%9}, {%0,%1,%2,%3};"
        : "+f"(c[0]), "+f"(c[1]), "+f"(c[2]), "+f"(c[3])
        : "r"(a[0]), "r"(a[1]), "r"(a[2]), "r"(a[3]), "r"(b[0]), "r"(b[1]));
}

__device__ __forceinline__ void cp_async16(void* smem_dst, const void* gsrc) {
    uint32_t d;
    asm("{ .reg .u64 t; cvta.to.shared.u64 t, %1; cvt.u32.u64 %0, t; }"
        : "=r"(d) : "l"(smem_dst));
    asm volatile("cp.async.cg.shared.global [%0], [%1], 16;" :: "r"(d), "l"(gsrc));
}
#define CP_COMMIT() asm volatile("cp.async.commit_group;" ::: "memory")
#define CP_WAIT(n)  asm volatile("cp.async.wait_group %0;" :: "n"(n) : "memory")

// ---------------------------------------------------------------------------
// Tensor-core GEMM via mma.sync: C[M,N] = A[M,K] @ W[N,K]^T, 3-term bf16 split.
// CTA tile 128x128, 8 warps (2m x 4n), warp tile 64x32, BK=32,
// cp.async double buffer. Requires M%128==0, N%128==0, K%32==0.
// Smem per array: [128 rows][40 bf16] (pad 32->40: conflict-free frag LDS).
// ---------------------------------------------------------------------------
#define LDS_STRIDE 40
#define ARR_BYTES  (128 * LDS_STRIDE * 2)       // 10240
#define STAGE_BYTES (4 * ARR_BYTES)             // 40960
#define GEMM_SMEM  (2 * STAGE_BYTES)            // 81920

__global__ __launch_bounds__(256)
void gemm_mma(const __nv_bfloat16* __restrict__ Ah, const __nv_bfloat16* __restrict__ Al,
              const __nv_bfloat16* __restrict__ Bh, const __nv_bfloat16* __restrict__ Bl,
              float* __restrict__ C, int M, int N, int K) {
    extern __shared__ char smem[];

    const int tid = threadIdx.x;
    const int wid = tid >> 5;
    const int lane = tid & 31;
    const int wm = (wid >> 2) * 64;     // warp m offset in tile (0 / 64)
    const int wn = (wid & 3) * 32;      // warp n offset in tile (0/32/64/96)
    const int lr = lane >> 2;           // 0..7
    const int lk = (lane & 3) * 2;      // 0,2,4,6

    const int bm = blockIdx.y * 128;
    const int bn = blockIdx.x * 128;

    // loader mapping: slot = tid + 256*u  -> row = slot/4, cw = slot%4 (16B word)
    const int l_row0 = tid >> 2;
    const int l_cw   = (tid & 3) * 8;   // bf16 offset of 16B word within 32

    auto stage_ptr = [&](int s, int arr) -> char* {
        return smem + s * STAGE_BYTES + arr * ARR_BYTES;
    };

    // Prefetch one K-chunk (32 cols) into stage s
    auto prefetch = [&](int s, int k0) {
        const __nv_bfloat16* gsrc[4] = {Ah, Al, Bh, Bl};
#pragma unroll
        for (int t = 0; t < 4; t++) {
            const int rb = (t < 2) ? bm : bn;
            char* base = stage_ptr(s, t);
#pragma unroll
            for (int u = 0; u < 2; u++) {
                int row = l_row0 + u * 64;
                cp_async16(base + row * (LDS_STRIDE * 2) + l_cw * 2,
                           gsrc[t] + (size_t)(rb + row) * K + k0 + l_cw);
            }
        }
        CP_COMMIT();
    };

    float acc[4][4][4];
#pragma unroll
    for (int mi = 0; mi < 4; mi++)
#pragma unroll
        for (int ni = 0; ni < 4; ni++)
#pragma unroll
            for (int r = 0; r < 4; r++) acc[mi][ni][r] = 0.f;

    const int nchunk = K / 32;
    prefetch(0, 0);

    for (int ch = 0; ch < nchunk; ch++) {
        const int s = ch & 1;
        if (ch + 1 < nchunk) {
            prefetch(s ^ 1, (ch + 1) * 32);
            CP_WAIT(1);
        } else {
            CP_WAIT(0);
        }
        __syncthreads();

        const __nv_bfloat16* sAh = (const __nv_bfloat16*)stage_ptr(s, 0);
        const __nv_bfloat16* sAl = (const __nv_bfloat16*)stage_ptr(s, 1);
        const __nv_bfloat16* sBh = (const __nv_bfloat16*)stage_ptr(s, 2);
        const __nv_bfloat16* sBl = (const __nv_bfloat16*)stage_ptr(s, 3);

#pragma unroll
        for (int kk = 0; kk < 2; kk++) {        // two k16 steps per chunk
            const int k0 = kk * 16;
            // B fragments for 4 n-frags (hi and lo)
            uint32_t bh[4][2], bl[4][2];
#pragma unroll
            for (int ni = 0; ni < 4; ni++) {
                int n = wn + ni * 8 + lr;
                bh[ni][0] = *(const uint32_t*)&sBh[n * LDS_STRIDE + k0 + lk];
                bh[ni][1] = *(const uint32_t*)&sBh[n * LDS_STRIDE + k0 + lk + 8];
                bl[ni][0] = *(const uint32_t*)&sBl[n * LDS_STRIDE + k0 + lk];
                bl[ni][1] = *(const uint32_t*)&sBl[n * LDS_STRIDE + k0 + lk + 8];
            }
#pragma unroll
            for (int mi = 0; mi < 4; mi++) {
                int r0 = wm + mi * 16 + lr;
                uint32_t ah[4], al[4];
                ah[0] = *(const uint32_t*)&sAh[(r0    ) * LDS_STRIDE + k0 + lk];
                ah[1] = *(const uint32_t*)&sAh[(r0 + 8) * LDS_STRIDE + k0 + lk];
                ah[2] = *(const uint32_t*)&sAh[(r0    ) * LDS_STRIDE + k0 + lk + 8];
                ah[3] = *(const uint32_t*)&sAh[(r0 + 8) * LDS_STRIDE + k0 + lk + 8];
                al[0] = *(const uint32_t*)&sAl[(r0    ) * LDS_STRIDE + k0 + lk];
                al[1] = *(const uint32_t*)&sAl[(r0 + 8) * LDS_STRIDE + k0 + lk];
                al[2] = *(const uint32_t*)&sAl[(r0    ) * LDS_STRIDE + k0 + lk + 8];
                al[3] = *(const uint32_t*)&sAl[(r0 + 8) * LDS_STRIDE + k0 + lk + 8];
#pragma unroll
                for (int ni = 0; ni < 4; ni++) {
                    mma_bf16(acc[mi][ni], ah, bh[ni]);
                    mma_bf16(acc[mi][ni], ah, bl[ni]);
                    mma_bf16(acc[mi][ni], al, bh[ni]);
                }
            }
        }
        __syncthreads();
    }

    // Epilogue: c0,c1 -> (row, col..col+1); c2,c3 -> (row+8, col..col+1)
#pragma unroll
    for (int mi = 0; mi < 4; mi++) {
        int row = bm + wm + mi * 16 + lr;
#pragma unroll
        for (int ni = 0; ni < 4; ni++) {
            int col = bn + wn + ni * 8 + lk;
            *(float2*)(C + (size_t)row * N + col) =
                make_float2(acc[mi][ni][0], acc[mi][ni][1]);
            *(float2*)(C + (size_t)(row + 8) * N + col) =
                make_float2(acc[mi][ni][2], acc[mi][ni][3]);
        }
    }
}

// ---------------------------------------------------------------------------
// Partial RoPE (first ROT=32 dims), in place.
// ---------------------------------------------------------------------------
__global__ void rope_kernel(float* __restrict__ x, const float* __restrict__ ct,
                            const float* __restrict__ st, int nheads, int total) {
    int idx = blockIdx.x * blockDim.x + threadIdx.x;
    if (idx >= total) return;
    int p  = idx & 15;
    int h  = (idx >> 4) % nheads;
    int bs = idx / (16 * nheads);
    float c = ct[bs * 32 + p];
    float s = st[bs * 32 + p];
    size_t base = ((size_t)bs * nheads + h) * 64;
    float x0 = x[base + p];
    float x1 = x[base + p + 16];
    x[base + p]      = x0 * c - x1 * s;
    x[base + p + 16] = x1 * c + x0 * s;
}

// ---------------------------------------------------------------------------
// Flash attention (fp32, causal, GQA).
// ---------------------------------------------------------------------------
#define SSTR 68
#define NEGBIG (-1e30f)

__global__ __launch_bounds__(256)
void flash_kernel(const float* __restrict__ q, const float* __restrict__ k,
                  const float* __restrict__ v, float* __restrict__ o) {
    extern __shared__ float sm[];
    float* Qst   = sm;
    float* Kst   = Qst + 64 * SSTR;
    float* Vs    = Kst + 64 * SSTR;
    float* St    = Vs  + 64 * SSTR;
    float* row_m = St  + 64 * SSTR;
    float* row_l = row_m + 64;
    float* row_a = row_l + 64;

    const int tid = threadIdx.x;
    const int qt  = blockIdx.x;
    const int bh  = blockIdx.y;
    const int b   = bh >> 5;
    const int h   = bh & 31;
    const int kvh = h >> 2;
    const int tr  = tid >> 4;
    const int tc  = tid & 15;
    const int lr  = tid >> 2;
    const int ld0 = (tid & 3) << 4;

    {
        const float* src = q + ((size_t)(b * SEQ + qt * 64 + lr) * (NHEAD * HDIM))
                             + h * HDIM + ld0;
#pragma unroll
        for (int u = 0; u < 4; u++) {
            float4 va = *(const float4*)(src + u * 4);
            int d0 = ld0 + u * 4;
            Qst[(d0 + 0) * SSTR + lr] = va.x * 0.125f;
            Qst[(d0 + 1) * SSTR + lr] = va.y * 0.125f;
            Qst[(d0 + 2) * SSTR + lr] = va.z * 0.125f;
            Qst[(d0 + 3) * SSTR + lr] = va.w * 0.125f;
        }
    }
    if (tid < 64) { row_m[tid] = NEGBIG; row_l[tid] = 0.f; }

    float acc[4][4];
#pragma unroll
    for (int i = 0; i < 4; i++)
#pragma unroll
        for (int j = 0; j < 4; j++) acc[i][j] = 0.f;

    __syncthreads();

    for (int kt = 0; kt <= qt; kt++) {
        {
            const float* ks = k + ((size_t)(b * SEQ + kt * 64 + lr) * (NKV * HDIM))
                                + kvh * HDIM + ld0;
            const float* vs = v + ((size_t)(b * SEQ + kt * 64 + lr) * (NKV * HDIM))
                                + kvh * HDIM + ld0;
#pragma unroll
            for (int u = 0; u < 4; u++) {
                int d0 = ld0 + u * 4;
                float4 va = *(const float4*)(ks + u * 4);
                Kst[(d0 + 0) * SSTR + lr] = va.x;
                Kst[(d0 + 1) * SSTR + lr] = va.y;
                Kst[(d0 + 2) * SSTR + lr] = va.z;
                Kst[(d0 + 3) * SSTR + lr] = va.w;
                float4 vb = *(const float4*)(vs + u * 4);
                *(float4*)&Vs[lr * SSTR + d0] = vb;
            }
        }
        __syncthreads();

        float s[4][4];
#pragma unroll
        for (int i = 0; i < 4; i++)
#pragma unroll
            for (int j = 0; j < 4; j++) s[i][j] = 0.f;
#pragma unroll 8
        for (int d = 0; d < 64; d++) {
            float qa[4], kb[4];
            *(float4*)qa = *(const float4*)&Qst[d * SSTR + tr * 4];
            *(float4*)kb = *(const float4*)&Kst[d * SSTR + tc * 4];
#pragma unroll
            for (int i = 0; i < 4; i++)
#pragma unroll
                for (int j = 0; j < 4; j++)
                    s[i][j] += qa[i] * kb[j];
        }
        const bool diag = (kt == qt);
#pragma unroll
        for (int j = 0; j < 4; j++) {
            int n = tc * 4 + j;
            float4 col;
            float* cp = &col.x;
#pragma unroll
            for (int i = 0; i < 4; i++) {
                int m = tr * 4 + i;
                float sv = s[i][j];
                if (diag && n > m) sv = NEGBIG;
                cp[i] = sv;
            }
            *(float4*)&St[n * SSTR + tr * 4] = col;
        }
        __syncthreads();

        if (tid < 64) {
            const int r = tid;
            float mx = row_m[r];
#pragma unroll 8
            for (int n = 0; n < 64; n++) mx = fmaxf(mx, St[n * SSTR + r]);
            float alpha = __expf(row_m[r] - mx);
            float l = row_l[r] * alpha;
            float sum = 0.f;
#pragma unroll 8
            for (int n = 0; n < 64; n++) {
                float p = __expf(St[n * SSTR + r] - mx);
                St[n * SSTR + r] = p;
                sum += p;
            }
            row_l[r] = l + sum;
            row_m[r] = mx;
            row_a[r] = alpha;
        }
        __syncthreads();

        float al[4];
#pragma unroll
        for (int i = 0; i < 4; i++) al[i] = row_a[tr * 4 + i];
#pragma unroll
        for (int i = 0; i < 4; i++)
#pragma unroll
            for (int j = 0; j < 4; j++) acc[i][j] *= al[i];
#pragma unroll 8
        for (int n = 0; n < 64; n++) {
            float p[4], vv[4];
            *(float4*)p  = *(const float4*)&St[n * SSTR + tr * 4];
            *(float4*)vv = *(const float4*)&Vs[n * SSTR + tc * 4];
#pragma unroll
            for (int i = 0; i < 4; i++)
#pragma unroll
                for (int j = 0; j < 4; j++)
                    acc[i][j] += p[i] * vv[j];
        }
        __syncthreads();
    }

#pragma unroll
    for (int i = 0; i < 4; i++) {
        int m = tr * 4 + i;
        float inv = 1.f / row_l[m];
        float* dst = o + ((size_t)(b * SEQ + qt * 64 + m) * (NHEAD * HDIM))
                       + h * HDIM + tc * 4;
        *(float4*)dst = make_float4(acc[i][0] * inv, acc[i][1] * inv,
                                    acc[i][2] * inv, acc[i][3] * inv);
    }
}

// ---------------------------------------------------------------------------
// Host launcher
// Inputs: 0 hidden 1 cos 2 sin 3 mask(unused) 4 Wq 5 Wk 6 Wv 7 Wo
// ---------------------------------------------------------------------------
extern "C" void kernel_launch(void* const* d_in, const int* in_sizes, int n_in,
                              void* d_out, int out_size) {
    const float* hidden = (const float*)d_in[0];
    const float* cosb   = (const float*)d_in[1];
    const float* sinb   = (const float*)d_in[2];
    const float* Wq     = (const float*)d_in[4];
    const float* Wk     = (const float*)d_in[5];
    const float* Wv     = (const float*)d_in[6];
    const float* Wo     = (const float*)d_in[7];
    float* out = (float*)d_out;

    float *qp, *kp, *vp, *ap;
    cudaGetSymbolAddress((void**)&qp, g_q);
    cudaGetSymbolAddress((void**)&kp, g_k);
    cudaGetSymbolAddress((void**)&vp, g_v);
    cudaGetSymbolAddress((void**)&ap, g_att);

    __nv_bfloat16 *ah, *al, *oh, *ol, *wqh, *wql, *wkh, *wkl, *wvh, *wvl, *woh, *wol;
    cudaGetSymbolAddress((void**)&ah, g_ah);   cudaGetSymbolAddress((void**)&al, g_al);
    cudaGetSymbolAddress((void**)&oh, g_oh);   cudaGetSymbolAddress((void**)&ol, g_ol);
    cudaGetSymbolAddress((void**)&wqh, g_wqh); cudaGetSymbolAddress((void**)&wql, g_wql);
    cudaGetSymbolAddress((void**)&wkh, g_wkh); cudaGetSymbolAddress((void**)&wkl, g_wkl);
    cudaGetSymbolAddress((void**)&wvh, g_wvh); cudaGetSymbolAddress((void**)&wvl, g_wvl);
    cudaGetSymbolAddress((void**)&woh, g_woh); cudaGetSymbolAddress((void**)&wol, g_wol);

    const int M = NBATCH * SEQ;  // 4096

    // bf16 hi/lo splits
    {
        int n4;
        n4 = (M * HID) / 4;
        split_kernel<<<(n4 + 255) / 256, 256>>>(hidden, ah, al, n4);
        n4 = (2048 * 2048) / 4;
        split_kernel<<<(n4 + 255) / 256, 256>>>(Wq, wqh, wql, n4);
        split_kernel<<<(n4 + 255) / 256, 256>>>(Wo, woh, wol, n4);
        n4 = (512 * 2048) / 4;
        split_kernel<<<(n4 + 255) / 256, 256>>>(Wk, wkh, wkl, n4);
        split_kernel<<<(n4 + 255) / 256, 256>>>(Wv, wvh, wvl, n4);
    }

    cudaFuncSetAttribute(gemm_mma, cudaFuncAttributeMaxDynamicSharedMemorySize,
                         GEMM_SMEM);

    // QKV projections (tensor cores via mma.sync)
    gemm_mma<<<dim3(2048 / 128, M / 128), 256, GEMM_SMEM>>>(ah, al, wqh, wql, qp, M, 2048, 2048);
    gemm_mma<<<dim3(512  / 128, M / 128), 256, GEMM_SMEM>>>(ah, al, wkh, wkl, kp, M, 512, 2048);
    gemm_mma<<<dim3(512  / 128, M / 128), 256, GEMM_SMEM>>>(ah, al, wvh, wvl, vp, M, 512, 2048);

    // Partial RoPE
    int totq = M * NHEAD * 16;
    rope_kernel<<<(totq + 255) / 256, 256>>>(qp, cosb, sinb, NHEAD, totq);
    int totk = M * NKV * 16;
    rope_kernel<<<(totk + 255) / 256, 256>>>(kp, cosb, sinb, NKV, totk);

    // Flash attention
    size_t smem = (size_t)4 * 64 * SSTR * sizeof(float) + 3 * 64 * sizeof(float);
    cudaFuncSetAttribute(flash_kernel, cudaFuncAttributeMaxDynamicSharedMemorySize,
                         (int)smem);
    flash_kernel<<<dim3(SEQ / 64, NBATCH * NHEAD), 256, smem>>>(qp, kp, vp, ap);

    // Output projection
    {
        int n4 = (M * 2048) / 4;
        split_kernel<<<(n4 + 255) / 256, 256>>>(ap, oh, ol, n4);
    }
    gemm_mma<<<dim3(2048 / 128, M / 128), 256, GEMM_SMEM>>>(oh, ol, woh, wol, out, M, 2048, 2048);
}

// round 5
// speedup vs baseline: 2.4270x; 1.4213x over previous
#include <cuda_runtime.h>
#include <cuda_bf16.h>
#include <cstdint>
#include <math.h>

// Problem: B=2, S=2048, HID=2048, H=32, KVH=8, D=64, G=4, ROT=32
#define NBATCH 2
#define SEQ    2048
#define HID    2048
#define NHEAD  32
#define NKV    8
#define HDIM   64

// ---------------------------------------------------------------------------
// Scratch (device globals; no allocations allowed)
// ---------------------------------------------------------------------------
__device__ float g_q[NBATCH*SEQ*NHEAD*HDIM];
__device__ float g_k[NBATCH*SEQ*NKV*HDIM];
__device__ float g_v[NBATCH*SEQ*NKV*HDIM];

// bf16 split buffers (hi/lo)
__device__ __nv_bfloat16 g_ah[4096*2048], g_al[4096*2048];     // hidden
__device__ __nv_bfloat16 g_oh[4096*2048], g_ol[4096*2048];     // attn out (flash writes)
__device__ __nv_bfloat16 g_wqh[2048*2048], g_wql[2048*2048];
__device__ __nv_bfloat16 g_wkh[512*2048],  g_wkl[512*2048];
__device__ __nv_bfloat16 g_wvh[512*2048],  g_wvl[512*2048];
__device__ __nv_bfloat16 g_woh[2048*2048], g_wol[2048*2048];
// attention operand splits
__device__ __nv_bfloat16 g_qh[NBATCH*SEQ*NHEAD*HDIM], g_ql[NBATCH*SEQ*NHEAD*HDIM];
__device__ __nv_bfloat16 g_kh[NBATCH*SEQ*NKV*HDIM],   g_kl[NBATCH*SEQ*NKV*HDIM];
__device__ __nv_bfloat16 g_vht[NBATCH*NKV*HDIM*SEQ],  g_vlt[NBATCH*NKV*HDIM*SEQ]; // [b][kvh][d][S]

// ---------------------------------------------------------------------------
// fp32 -> (bf16 hi, bf16 lo) split with scale, vectorized x4
// ---------------------------------------------------------------------------
__global__ void split_kernel(const float* __restrict__ x,
                             __nv_bfloat16* __restrict__ hi,
                             __nv_bfloat16* __restrict__ lo, int n4, float scale) {
    int i = blockIdx.x * blockDim.x + threadIdx.x;
    if (i >= n4) return;
    float4 v = ((const float4*)x)[i];
    v.x *= scale; v.y *= scale; v.z *= scale; v.w *= scale;
    __nv_bfloat16 h0 = __float2bfloat16(v.x);
    __nv_bfloat16 h1 = __float2bfloat16(v.y);
    __nv_bfloat16 h2 = __float2bfloat16(v.z);
    __nv_bfloat16 h3 = __float2bfloat16(v.w);
    __nv_bfloat16 l0 = __float2bfloat16(v.x - __bfloat162float(h0));
    __nv_bfloat16 l1 = __float2bfloat16(v.y - __bfloat162float(h1));
    __nv_bfloat16 l2 = __float2bfloat16(v.z - __bfloat162float(h2));
    __nv_bfloat16 l3 = __float2bfloat16(v.w - __bfloat162float(h3));
    __nv_bfloat162* hp = (__nv_bfloat162*)(hi + (size_t)i * 4);
    __nv_bfloat162* lp = (__nv_bfloat162*)(lo + (size_t)i * 4);
    hp[0] = __nv_bfloat162(h0, h1); hp[1] = __nv_bfloat162(h2, h3);
    lp[0] = __nv_bfloat162(l0, l1); lp[1] = __nv_bfloat162(l2, l3);
}

// ---------------------------------------------------------------------------
// V transpose + split: v[b][s][kvh][d] fp32 -> vht/vlt[b][kvh][d][S] bf16
// ---------------------------------------------------------------------------
__global__ void vsplitT_kernel(const float* __restrict__ v,
                               __nv_bfloat16* __restrict__ vh,
                               __nv_bfloat16* __restrict__ vl) {
    __shared__ float t[32][33];
    const int bkv = blockIdx.z;
    const int b = bkv / NKV, kvh = bkv % NKV;
    const int s0 = blockIdx.x * 32, d0 = blockIdx.y * 32;
    const int tx = threadIdx.x, ty = threadIdx.y;   // 32 x 8
#pragma unroll
    for (int j = 0; j < 32; j += 8) {
        int s = s0 + ty + j;
        t[ty + j][tx] = v[((size_t)(b * SEQ + s) * NKV + kvh) * HDIM + d0 + tx];
    }
    __syncthreads();
#pragma unroll
    for (int j = 0; j < 32; j += 8) {
        int d = d0 + ty + j;
        float val = t[tx][ty + j];
        __nv_bfloat16 h = __float2bfloat16(val);
        size_t o = ((size_t)(b * NKV + kvh) * HDIM + d) * SEQ + s0 + tx;
        vh[o] = h;
        vl[o] = __float2bfloat16(val - __bfloat162float(h));
    }
}

// ---------------------------------------------------------------------------
// mma.sync helpers
// ---------------------------------------------------------------------------
__device__ __forceinline__ void mma_bf16(float* c, const uint32_t* a, const uint32_t* b) {
    asm volatile(
        "mma.sync.aligned.m16n8k16.row.col.f32.bf16.bf16.f32 "
        "{%0,%1,%2,%3}, {%4,%5,%6,%7}, {%8,%9}, {%0,%1,%2,%3};"
        : "+f"(c[0]), "+f"(c[1]), "+f"(c[2]), "+f"(c[3])
        : "r"(a[0]), "r"(a[1]), "r"(a[2]), "r"(a[3]), "r"(b[0]), "r"(b[1]));
}

__device__ __forceinline__ void cp_async16(void* smem_dst, const void* gsrc) {
    uint32_t d;
    asm("{ .reg .u64 t; cvta.to.shared.u64 t, %1; cvt.u32.u64 %0, t; }"
        : "=r"(d) : "l"(smem_dst));
    asm volatile("cp.async.cg.shared.global [%0], [%1], 16;" :: "r"(d), "l"(gsrc));
}
#define CP_COMMIT() asm volatile("cp.async.commit_group;" ::: "memory")
#define CP_WAIT(n)  asm volatile("cp.async.wait_group %0;" :: "n"(n) : "memory")

// ---------------------------------------------------------------------------
// Tensor-core GEMM (unchanged, known-good): C = A @ W^T, 3-term bf16 split.
// ---------------------------------------------------------------------------
#define LDS_STRIDE 40
#define ARR_BYTES  (128 * LDS_STRIDE * 2)
#define STAGE_BYTES (4 * ARR_BYTES)
#define GEMM_SMEM  (2 * STAGE_BYTES)

__global__ __launch_bounds__(256)
void gemm_mma(const __nv_bfloat16* __restrict__ Ah, const __nv_bfloat16* __restrict__ Al,
              const __nv_bfloat16* __restrict__ Bh, const __nv_bfloat16* __restrict__ Bl,
              float* __restrict__ C, int M, int N, int K) {
    extern __shared__ char smem[];

    const int tid = threadIdx.x;
    const int wid = tid >> 5;
    const int lane = tid & 31;
    const int wm = (wid >> 2) * 64;
    const int wn = (wid & 3) * 32;
    const int lr = lane >> 2;
    const int lk = (lane & 3) * 2;

    const int bm = blockIdx.y * 128;
    const int bn = blockIdx.x * 128;

    const int l_row0 = tid >> 2;
    const int l_cw   = (tid & 3) * 8;

    auto stage_ptr = [&](int s, int arr) -> char* {
        return smem + s * STAGE_BYTES + arr * ARR_BYTES;
    };

    auto prefetch = [&](int s, int k0) {
        const __nv_bfloat16* gsrc[4] = {Ah, Al, Bh, Bl};
#pragma unroll
        for (int t = 0; t < 4; t++) {
            const int rb = (t < 2) ? bm : bn;
            char* base = stage_ptr(s, t);
#pragma unroll
            for (int u = 0; u < 2; u++) {
                int row = l_row0 + u * 64;
                cp_async16(base + row * (LDS_STRIDE * 2) + l_cw * 2,
                           gsrc[t] + (size_t)(rb + row) * K + k0 + l_cw);
            }
        }
        CP_COMMIT();
    };

    float acc[4][4][4];
#pragma unroll
    for (int mi = 0; mi < 4; mi++)
#pragma unroll
        for (int ni = 0; ni < 4; ni++)
#pragma unroll
            for (int r = 0; r < 4; r++) acc[mi][ni][r] = 0.f;

    const int nchunk = K / 32;
    prefetch(0, 0);

    for (int ch = 0; ch < nchunk; ch++) {
        const int s = ch & 1;
        if (ch + 1 < nchunk) {
            prefetch(s ^ 1, (ch + 1) * 32);
            CP_WAIT(1);
        } else {
            CP_WAIT(0);
        }
        __syncthreads();

        const __nv_bfloat16* sAh = (const __nv_bfloat16*)stage_ptr(s, 0);
        const __nv_bfloat16* sAl = (const __nv_bfloat16*)stage_ptr(s, 1);
        const __nv_bfloat16* sBh = (const __nv_bfloat16*)stage_ptr(s, 2);
        const __nv_bfloat16* sBl = (const __nv_bfloat16*)stage_ptr(s, 3);

#pragma unroll
        for (int kk = 0; kk < 2; kk++) {
            const int k0 = kk * 16;
            uint32_t bh[4][2], bl[4][2];
#pragma unroll
            for (int ni = 0; ni < 4; ni++) {
                int n = wn + ni * 8 + lr;
                bh[ni][0] = *(const uint32_t*)&sBh[n * LDS_STRIDE + k0 + lk];
                bh[ni][1] = *(const uint32_t*)&sBh[n * LDS_STRIDE + k0 + lk + 8];
                bl[ni][0] = *(const uint32_t*)&sBl[n * LDS_STRIDE + k0 + lk];
                bl[ni][1] = *(const uint32_t*)&sBl[n * LDS_STRIDE + k0 + lk + 8];
            }
#pragma unroll
            for (int mi = 0; mi < 4; mi++) {
                int r0 = wm + mi * 16 + lr;
                uint32_t ah[4], al[4];
                ah[0] = *(const uint32_t*)&sAh[(r0    ) * LDS_STRIDE + k0 + lk];
                ah[1] = *(const uint32_t*)&sAh[(r0 + 8) * LDS_STRIDE + k0 + lk];
                ah[2] = *(const uint32_t*)&sAh[(r0    ) * LDS_STRIDE + k0 + lk + 8];
                ah[3] = *(const uint32_t*)&sAh[(r0 + 8) * LDS_STRIDE + k0 + lk + 8];
                al[0] = *(const uint32_t*)&sAl[(r0    ) * LDS_STRIDE + k0 + lk];
                al[1] = *(const uint32_t*)&sAl[(r0 + 8) * LDS_STRIDE + k0 + lk];
                al[2] = *(const uint32_t*)&sAl[(r0    ) * LDS_STRIDE + k0 + lk + 8];
                al[3] = *(const uint32_t*)&sAl[(r0 + 8) * LDS_STRIDE + k0 + lk + 8];
#pragma unroll
                for (int ni = 0; ni < 4; ni++) {
                    mma_bf16(acc[mi][ni], ah, bh[ni]);
                    mma_bf16(acc[mi][ni], ah, bl[ni]);
                    mma_bf16(acc[mi][ni], al, bh[ni]);
                }
            }
        }
        __syncthreads();
    }

#pragma unroll
    for (int mi = 0; mi < 4; mi++) {
        int row = bm + wm + mi * 16 + lr;
#pragma unroll
        for (int ni = 0; ni < 4; ni++) {
            int col = bn + wn + ni * 8 + lk;
            *(float2*)(C + (size_t)row * N + col) =
                make_float2(acc[mi][ni][0], acc[mi][ni][1]);
            *(float2*)(C + (size_t)(row + 8) * N + col) =
                make_float2(acc[mi][ni][2], acc[mi][ni][3]);
        }
    }
}

// ---------------------------------------------------------------------------
// Partial RoPE (first ROT=32 dims), in place.
// ---------------------------------------------------------------------------
__global__ void rope_kernel(float* __restrict__ x, const float* __restrict__ ct,
                            const float* __restrict__ st, int nheads, int total) {
    int idx = blockIdx.x * blockDim.x + threadIdx.x;
    if (idx >= total) return;
    int p  = idx & 15;
    int h  = (idx >> 4) % nheads;
    int bs = idx / (16 * nheads);
    float c = ct[bs * 32 + p];
    float s = st[bs * 32 + p];
    size_t base = ((size_t)bs * nheads + h) * 64;
    float x0 = x[base + p];
    float x1 = x[base + p + 16];
    x[base + p]      = x0 * c - x1 * s;
    x[base + p + 16] = x1 * c + x0 * s;
}

// ---------------------------------------------------------------------------
// Tensor-core flash attention (causal, GQA), bf16 3-term splits.
// Grid (32, 64): qt = 31-bx (longest first), bh = by. 256 threads, 8 warps 2mx4n.
// Tile: 64 q rows x 64 keys. Q pre-scaled by 0.125 in split.
// ---------------------------------------------------------------------------
#define KSTR  72   // bf16 smem stride (36 words -> conflict-free frag LDS)
#define SSTRF 66   // fp32 score stride
#define NEGBIG (-1e30f)
#define FLASH_SMEM (8 * 64 * KSTR * 2 + 64 * SSTRF * 4 + 3 * 64 * 4)

__global__ __launch_bounds__(256)
void flash_tc(const __nv_bfloat16* __restrict__ qh, const __nv_bfloat16* __restrict__ ql,
              const __nv_bfloat16* __restrict__ kh, const __nv_bfloat16* __restrict__ kl,
              const __nv_bfloat16* __restrict__ vht, const __nv_bfloat16* __restrict__ vlt,
              __nv_bfloat16* __restrict__ oh, __nv_bfloat16* __restrict__ ol) {
    extern __shared__ char smc[];
    __nv_bfloat16* sQh = (__nv_bfloat16*)smc;
    __nv_bfloat16* sQl = sQh + 64 * KSTR;
    __nv_bfloat16* sKh = sQl + 64 * KSTR;
    __nv_bfloat16* sKl = sKh + 64 * KSTR;
    __nv_bfloat16* sVh = sKl + 64 * KSTR;   // [d][key]
    __nv_bfloat16* sVl = sVh + 64 * KSTR;
    __nv_bfloat16* sPh = sVl + 64 * KSTR;
    __nv_bfloat16* sPl = sPh + 64 * KSTR;
    float* sS    = (float*)(sPl + 64 * KSTR);
    float* row_m = sS + 64 * SSTRF;
    float* row_l = row_m + 64;
    float* row_a = row_l + 64;

    const int tid  = threadIdx.x;
    const int wid  = tid >> 5;
    const int lane = tid & 31;
    const int wm = (wid >> 2) * 32;     // warp m offset (0/32)
    const int wn = (wid & 3) * 16;      // warp n offset (0/16/32/48)
    const int lr = lane >> 2;
    const int lk = (lane & 3) * 2;

    const int qt  = gridDim.x - 1 - blockIdx.x;
    const int bh  = blockIdx.y;
    const int b   = bh >> 5;
    const int h   = bh & 31;
    const int kvh = h >> 2;

    // Q tile load (once): 64 rows x 8 uint4 per array
#pragma unroll
    for (int u = 0; u < 2; u++) {
        int slot = tid + 256 * u;
        int row = slot >> 3, cw = slot & 7;
        const size_t go = ((size_t)(b * SEQ + qt * 64 + row) * NHEAD + h) * HDIM + cw * 8;
        cp_async16(sQh + row * KSTR + cw * 8, qh + go);
        cp_async16(sQl + row * KSTR + cw * 8, ql + go);
    }
    CP_COMMIT();

    if (tid < 64) { row_m[tid] = NEGBIG; row_l[tid] = 0.f; }

    float oacc[2][2][4];
#pragma unroll
    for (int mi = 0; mi < 2; mi++)
#pragma unroll
        for (int ni = 0; ni < 2; ni++)
#pragma unroll
            for (int r = 0; r < 4; r++) oacc[mi][ni][r] = 0.f;

    for (int kt = 0; kt <= qt; kt++) {
        // K and V(transposed) tile loads
#pragma unroll
        for (int u = 0; u < 2; u++) {
            int slot = tid + 256 * u;
            int row = slot >> 3, cw = slot & 7;
            const size_t gk = ((size_t)(b * SEQ + kt * 64 + row) * NKV + kvh) * HDIM + cw * 8;
            cp_async16(sKh + row * KSTR + cw * 8, kh + gk);
            cp_async16(sKl + row * KSTR + cw * 8, kl + gk);
            const size_t gv = ((size_t)(b * NKV + kvh) * HDIM + row) * SEQ + kt * 64 + cw * 8;
            cp_async16(sVh + row * KSTR + cw * 8, vht + gv);
            cp_async16(sVl + row * KSTR + cw * 8, vlt + gv);
        }
        CP_COMMIT();
        CP_WAIT(0);
        __syncthreads();

        // ---- S = Q @ K^T (3-term) ----
        float sacc[2][2][4];
#pragma unroll
        for (int mi = 0; mi < 2; mi++)
#pragma unroll
            for (int ni = 0; ni < 2; ni++)
#pragma unroll
                for (int r = 0; r < 4; r++) sacc[mi][ni][r] = 0.f;

#pragma unroll
        for (int kk = 0; kk < 4; kk++) {
            const int k0 = kk * 16;
            uint32_t kbh[2][2], kbl[2][2];
#pragma unroll
            for (int ni = 0; ni < 2; ni++) {
                int n = wn + ni * 8 + lr;
                kbh[ni][0] = *(const uint32_t*)&sKh[n * KSTR + k0 + lk];
                kbh[ni][1] = *(const uint32_t*)&sKh[n * KSTR + k0 + lk + 8];
                kbl[ni][0] = *(const uint32_t*)&sKl[n * KSTR + k0 + lk];
                kbl[ni][1] = *(const uint32_t*)&sKl[n * KSTR + k0 + lk + 8];
            }
#pragma unroll
            for (int mi = 0; mi < 2; mi++) {
                int r0 = wm + mi * 16 + lr;
                uint32_t qah[4], qal[4];
                qah[0] = *(const uint32_t*)&sQh[(r0    ) * KSTR + k0 + lk];
                qah[1] = *(const uint32_t*)&sQh[(r0 + 8) * KSTR + k0 + lk];
                qah[2] = *(const uint32_t*)&sQh[(r0    ) * KSTR + k0 + lk + 8];
                qah[3] = *(const uint32_t*)&sQh[(r0 + 8) * KSTR + k0 + lk + 8];
                qal[0] = *(const uint32_t*)&sQl[(r0    ) * KSTR + k0 + lk];
                qal[1] = *(const uint32_t*)&sQl[(r0 + 8) * KSTR + k0 + lk];
                qal[2] = *(const uint32_t*)&sQl[(r0    ) * KSTR + k0 + lk + 8];
                qal[3] = *(const uint32_t*)&sQl[(r0 + 8) * KSTR + k0 + lk + 8];
#pragma unroll
                for (int ni = 0; ni < 2; ni++) {
                    mma_bf16(sacc[mi][ni], qah, kbh[ni]);
                    mma_bf16(sacc[mi][ni], qah, kbl[ni]);
                    mma_bf16(sacc[mi][ni], qal, kbh[ni]);
                }
            }
        }

        // ---- mask + store scores to smem ----
        const bool diag = (kt == qt);
#pragma unroll
        for (int mi = 0; mi < 2; mi++) {
#pragma unroll
            for (int ni = 0; ni < 2; ni++) {
                int r = wm + mi * 16 + lr;
                int c = wn + ni * 8 + lk;
                float s0 = sacc[mi][ni][0], s1 = sacc[mi][ni][1];
                float s2 = sacc[mi][ni][2], s3 = sacc[mi][ni][3];
                if (diag) {
                    if (c     > r)     s0 = NEGBIG;
                    if (c + 1 > r)     s1 = NEGBIG;
                    if (c     > r + 8) s2 = NEGBIG;
                    if (c + 1 > r + 8) s3 = NEGBIG;
                }
                *(float2*)&sS[r * SSTRF + c]       = make_float2(s0, s1);
                *(float2*)&sS[(r + 8) * SSTRF + c] = make_float2(s2, s3);
            }
        }
        __syncthreads();

        // ---- online softmax: 4 threads per row, 16 cols each ----
        {
            const int row = tid >> 2, seg = tid & 3;
            const float* srow = sS + row * SSTRF + seg * 16;
            float mx = NEGBIG;
#pragma unroll
            for (int j = 0; j < 16; j++) mx = fmaxf(mx, srow[j]);
            mx = fmaxf(mx, __shfl_xor_sync(0xFFFFFFFF, mx, 1));
            mx = fmaxf(mx, __shfl_xor_sync(0xFFFFFFFF, mx, 2));
            const float mprev = row_m[row];
            const float mnew = fmaxf(mprev, mx);
            float sum = 0.f;
            __nv_bfloat16* ph = sPh + row * KSTR + seg * 16;
            __nv_bfloat16* pl = sPl + row * KSTR + seg * 16;
#pragma unroll
            for (int j = 0; j < 16; j++) {
                float p = __expf(srow[j] - mnew);
                sum += p;
                __nv_bfloat16 hp = __float2bfloat16(p);
                ph[j] = hp;
                pl[j] = __float2bfloat16(p - __bfloat162float(hp));
            }
            sum += __shfl_xor_sync(0xFFFFFFFF, sum, 1);
            sum += __shfl_xor_sync(0xFFFFFFFF, sum, 2);
            if (seg == 0) {
                float alpha = __expf(mprev - mnew);
                row_a[row] = alpha;
                row_l[row] = row_l[row] * alpha + sum;
                row_m[row] = mnew;
            }
        }
        __syncthreads();

        // ---- rescale O, accumulate P @ V (3-term) ----
#pragma unroll
        for (int mi = 0; mi < 2; mi++) {
            int r0 = wm + mi * 16 + lr;
            float a0 = row_a[r0], a1 = row_a[r0 + 8];
#pragma unroll
            for (int ni = 0; ni < 2; ni++) {
                oacc[mi][ni][0] *= a0; oacc[mi][ni][1] *= a0;
                oacc[mi][ni][2] *= a1; oacc[mi][ni][3] *= a1;
            }
        }
#pragma unroll
        for (int kk = 0; kk < 4; kk++) {
            const int k0 = kk * 16;
            uint32_t vbh[2][2], vbl[2][2];
#pragma unroll
            for (int ni = 0; ni < 2; ni++) {
                int n = wn + ni * 8 + lr;     // d column
                vbh[ni][0] = *(const uint32_t*)&sVh[n * KSTR + k0 + lk];
                vbh[ni][1] = *(const uint32_t*)&sVh[n * KSTR + k0 + lk + 8];
                vbl[ni][0] = *(const uint32_t*)&sVl[n * KSTR + k0 + lk];
                vbl[ni][1] = *(const uint32_t*)&sVl[n * KSTR + k0 + lk + 8];
            }
#pragma unroll
            for (int mi = 0; mi < 2; mi++) {
                int r0 = wm + mi * 16 + lr;
                uint32_t pah[4], pal[4];
                pah[0] = *(const uint32_t*)&sPh[(r0    ) * KSTR + k0 + lk];
                pah[1] = *(const uint32_t*)&sPh[(r0 + 8) * KSTR + k0 + lk];
                pah[2] = *(const uint32_t*)&sPh[(r0    ) * KSTR + k0 + lk + 8];
                pah[3] = *(const uint32_t*)&sPh[(r0 + 8) * KSTR + k0 + lk + 8];
                pal[0] = *(const uint32_t*)&sPl[(r0    ) * KSTR + k0 + lk];
                pal[1] = *(const uint32_t*)&sPl[(r0 + 8) * KSTR + k0 + lk];
                pal[2] = *(const uint32_t*)&sPl[(r0    ) * KSTR + k0 + lk + 8];
                pal[3] = *(const uint32_t*)&sPl[(r0 + 8) * KSTR + k0 + lk + 8];
#pragma unroll
                for (int ni = 0; ni < 2; ni++) {
                    mma_bf16(oacc[mi][ni], pah, vbh[ni]);
                    mma_bf16(oacc[mi][ni], pah, vbl[ni]);
                    mma_bf16(oacc[mi][ni], pal, vbh[ni]);
                }
            }
        }
        __syncthreads();
    }

    // ---- normalize + write bf16 hi/lo output [b][s][h][d] ----
#pragma unroll
    for (int mi = 0; mi < 2; mi++) {
        int r = wm + mi * 16 + lr;
        float inv0 = 1.f / row_l[r];
        float inv1 = 1.f / row_l[r + 8];
#pragma unroll
        for (int ni = 0; ni < 2; ni++) {
            int c = wn + ni * 8 + lk;
            size_t o0 = ((size_t)(b * SEQ + qt * 64 + r) * NHEAD + h) * HDIM + c;
            size_t o1 = ((size_t)(b * SEQ + qt * 64 + r + 8) * NHEAD + h) * HDIM + c;
            float v0 = oacc[mi][ni][0] * inv0, v1 = oacc[mi][ni][1] * inv0;
            float v2 = oacc[mi][ni][2] * inv1, v3 = oacc[mi][ni][3] * inv1;
            __nv_bfloat16 h0 = __float2bfloat16(v0), h1 = __float2bfloat16(v1);
            __nv_bfloat16 h2 = __float2bfloat16(v2), h3 = __float2bfloat16(v3);
            *(__nv_bfloat162*)(oh + o0) = __nv_bfloat162(h0, h1);
            *(__nv_bfloat162*)(oh + o1) = __nv_bfloat162(h2, h3);
            *(__nv_bfloat162*)(ol + o0) = __nv_bfloat162(
                __float2bfloat16(v0 - __bfloat162float(h0)),
                __float2bfloat16(v1 - __bfloat162float(h1)));
            *(__nv_bfloat162*)(ol + o1) = __nv_bfloat162(
                __float2bfloat16(v2 - __bfloat162float(h2)),
                __float2bfloat16(v3 - __bfloat162float(h3)));
        }
    }
}

// ---------------------------------------------------------------------------
// Host launcher
// Inputs: 0 hidden 1 cos 2 sin 3 mask(unused) 4 Wq 5 Wk 6 Wv 7 Wo
// ---------------------------------------------------------------------------
extern "C" void kernel_launch(void* const* d_in, const int* in_sizes, int n_in,
                              void* d_out, int out_size) {
    const float* hidden = (const float*)d_in[0];
    const float* cosb   = (const float*)d_in[1];
    const float* sinb   = (const float*)d_in[2];
    const float* Wq     = (const float*)d_in[4];
    const float* Wk     = (const float*)d_in[5];
    const float* Wv     = (const float*)d_in[6];
    const float* Wo     = (const float*)d_in[7];
    float* out = (float*)d_out;

    float *qp, *kp, *vp;
    cudaGetSymbolAddress((void**)&qp, g_q);
    cudaGetSymbolAddress((void**)&kp, g_k);
    cudaGetSymbolAddress((void**)&vp, g_v);

    __nv_bfloat16 *ah, *al, *oh, *ol, *wqh, *wql, *wkh, *wkl, *wvh, *wvl, *woh, *wol;
    __nv_bfloat16 *qhp, *qlp, *khp, *klp, *vhtp, *vltp;
    cudaGetSymbolAddress((void**)&ah, g_ah);   cudaGetSymbolAddress((void**)&al, g_al);
    cudaGetSymbolAddress((void**)&oh, g_oh);   cudaGetSymbolAddress((void**)&ol, g_ol);
    cudaGetSymbolAddress((void**)&wqh, g_wqh); cudaGetSymbolAddress((void**)&wql, g_wql);
    cudaGetSymbolAddress((void**)&wkh, g_wkh); cudaGetSymbolAddress((void**)&wkl, g_wkl);
    cudaGetSymbolAddress((void**)&wvh, g_wvh); cudaGetSymbolAddress((void**)&wvl, g_wvl);
    cudaGetSymbolAddress((void**)&woh, g_woh); cudaGetSymbolAddress((void**)&wol, g_wol);
    cudaGetSymbolAddress((void**)&qhp, g_qh);  cudaGetSymbolAddress((void**)&qlp, g_ql);
    cudaGetSymbolAddress((void**)&khp, g_kh);  cudaGetSymbolAddress((void**)&klp, g_kl);
    cudaGetSymbolAddress((void**)&vhtp, g_vht); cudaGetSymbolAddress((void**)&vltp, g_vlt);

    const int M = NBATCH * SEQ;  // 4096

    // bf16 hi/lo splits of inputs
    {
        int n4;
        n4 = (M * HID) / 4;
        split_kernel<<<(n4 + 255) / 256, 256>>>(hidden, ah, al, n4, 1.f);
        n4 = (2048 * 2048) / 4;
        split_kernel<<<(n4 + 255) / 256, 256>>>(Wq, wqh, wql, n4, 1.f);
        split_kernel<<<(n4 + 255) / 256, 256>>>(Wo, woh, wol, n4, 1.f);
        n4 = (512 * 2048) / 4;
        split_kernel<<<(n4 + 255) / 256, 256>>>(Wk, wkh, wkl, n4, 1.f);
        split_kernel<<<(n4 + 255) / 256, 256>>>(Wv, wvh, wvl, n4, 1.f);
    }

    cudaFuncSetAttribute(gemm_mma, cudaFuncAttributeMaxDynamicSharedMemorySize,
                         GEMM_SMEM);

    // QKV projections
    gemm_mma<<<dim3(2048 / 128, M / 128), 256, GEMM_SMEM>>>(ah, al, wqh, wql, qp, M, 2048, 2048);
    gemm_mma<<<dim3(512  / 128, M / 128), 256, GEMM_SMEM>>>(ah, al, wkh, wkl, kp, M, 512, 2048);
    gemm_mma<<<dim3(512  / 128, M / 128), 256, GEMM_SMEM>>>(ah, al, wvh, wvl, vp, M, 512, 2048);

    // Partial RoPE
    int totq = M * NHEAD * 16;
    rope_kernel<<<(totq + 255) / 256, 256>>>(qp, cosb, sinb, NHEAD, totq);
    int totk = M * NKV * 16;
    rope_kernel<<<(totk + 255) / 256, 256>>>(kp, cosb, sinb, NKV, totk);

    // Attention operand splits (Q scaled by 1/sqrt(D))
    {
        int n4 = (M * NHEAD * HDIM) / 4;
        split_kernel<<<(n4 + 255) / 256, 256>>>(qp, qhp, qlp, n4, 0.125f);
        n4 = (M * NKV * HDIM) / 4;
        split_kernel<<<(n4 + 255) / 256, 256>>>(kp, khp, klp, n4, 1.f);
        vsplitT_kernel<<<dim3(SEQ / 32, HDIM / 32, NBATCH * NKV), dim3(32, 8)>>>(vp, vhtp, vltp);
    }

    // Tensor-core flash attention
    cudaFuncSetAttribute(flash_tc, cudaFuncAttributeMaxDynamicSharedMemorySize,
                         FLASH_SMEM);
    flash_tc<<<dim3(SEQ / 64, NBATCH * NHEAD), 256, FLASH_SMEM>>>(
        qhp, qlp, khp, klp, vhtp, vltp, oh, ol);

    // Output projection
    gemm_mma<<<dim3(2048 / 128, M / 128), 256, GEMM_SMEM>>>(oh, ol, woh, wol, out, M, 2048, 2048);
}